// round 1
// baseline (speedup 1.0000x reference)
#include <cuda_runtime.h>
#include <cuda_bf16.h>

#define TSEQ   2048
#define BATCH  4096
#define HDIM   32
#define NB     4      // batch rows per warp
#define STAGE  16     // timesteps staged per x-load

// ---------- packed f32x2 helpers ----------
__device__ __forceinline__ unsigned long long pack2(float lo, float hi) {
    unsigned long long r;
    asm("mov.b64 %0, {%1, %2};" : "=l"(r) : "f"(lo), "f"(hi));
    return r;
}
__device__ __forceinline__ void unpack2(unsigned long long v, float& lo, float& hi) {
    asm("mov.b64 {%0, %1}, %2;" : "=f"(lo), "=f"(hi) : "l"(v));
}
__device__ __forceinline__ unsigned long long ffma2(unsigned long long a,
                                                    unsigned long long b,
                                                    unsigned long long c) {
    unsigned long long d;
    asm("fma.rn.f32x2 %0, %1, %2, %3;" : "=l"(d) : "l"(a), "l"(b), "l"(c));
    return d;
}

// ---------- fast activations (ex2/rcp approx: ~1e-6 rel err) ----------
__device__ __forceinline__ float fast_sig(float x) {
    float e, r;
    asm("ex2.approx.f32 %0, %1;" : "=f"(e) : "f"(-1.4426950408889634f * x));
    asm("rcp.approx.f32 %0, %1;" : "=f"(r) : "f"(1.0f + e));
    return r;  // 1 / (1 + exp(-x))
}
__device__ __forceinline__ float fast_tanh(float x) {
    return fmaf(2.0f, fast_sig(2.0f * x), -1.0f);
}

// One warp per block; warp handles NB consecutive batch rows.
// Lane j owns h-index j. Gates packed (i,f) and (g,o) into f32x2.
__global__ void __launch_bounds__(32, 1)
lstm_warp_kernel(const float* __restrict__ x,
                 const float* __restrict__ W_ih,
                 const float* __restrict__ W_hh,
                 const float* __restrict__ b_ih,
                 const float* __restrict__ b_hh,
                 float* __restrict__ out)
{
    // h stored duplicated (v,v) so LDS.128 yields two ready-to-use f32x2 broadcasts
    __shared__ __align__(16) unsigned long long hdup[NB][HDIM];
    // x staged duplicated; pad inner dim 3 -> 4 for 16B-aligned 32B stride
    __shared__ __align__(16) unsigned long long xdup[NB][STAGE][4];

    const int lane = threadIdx.x & 31;
    const int b0   = blockIdx.x * NB;

    // PyTorch gate rows for this lane: i, f, g, o
    const int r0 = lane;
    const int r1 = HDIM + lane;
    const int r2 = 2 * HDIM + lane;
    const int r3 = 3 * HDIM + lane;

    // ---- preload weights into registers, gate-pair packed ----
    unsigned long long wif[HDIM], wgo[HDIM];
#pragma unroll
    for (int k = 0; k < HDIM; k++) {
        wif[k] = pack2(W_hh[r0 * HDIM + k], W_hh[r1 * HDIM + k]);
        wgo[k] = pack2(W_hh[r2 * HDIM + k], W_hh[r3 * HDIM + k]);
    }
    unsigned long long wxif[3], wxgo[3];
#pragma unroll
    for (int i = 0; i < 3; i++) {
        wxif[i] = pack2(W_ih[r0 * 3 + i], W_ih[r1 * 3 + i]);
        wxgo[i] = pack2(W_ih[r2 * 3 + i], W_ih[r3 * 3 + i]);
    }
    const unsigned long long bias_if = pack2(b_ih[r0] + b_hh[r0], b_ih[r1] + b_hh[r1]);
    const unsigned long long bias_go = pack2(b_ih[r2] + b_hh[r2], b_ih[r3] + b_hh[r3]);

    float c[NB], h[NB];
#pragma unroll
    for (int b = 0; b < NB; b++) {
        c[b] = 0.0f;
        h[b] = 0.0f;
        hdup[b][lane] = 0ull;
    }
    __syncwarp();

    for (int t0 = 0; t0 < TSEQ; t0 += STAGE) {
        // ---- stage STAGE steps of x, pre-duplicated, coalesced loads ----
#pragma unroll
        for (int it = 0; it < (NB * STAGE * 3 + 31) / 32; it++) {
            int idx = it * 32 + lane;
            if (idx < NB * STAGE * 3) {
                int b  = idx / (STAGE * 3);
                int p  = idx % (STAGE * 3);
                int tl = p / 3;
                int i  = p % 3;
                float v = x[(size_t)(b0 + b) * TSEQ * 3 + (size_t)(t0 + tl) * 3 + i];
                xdup[b][tl][i] = pack2(v, v);
            }
        }
        __syncwarp();

#pragma unroll 1
        for (int tt = 0; tt < STAGE; tt++) {
            unsigned long long aif[NB], ago[NB];

            // ---- input-gate contribution + bias ----
#pragma unroll
            for (int b = 0; b < NB; b++) {
                unsigned long long x0 = xdup[b][tt][0];
                unsigned long long x1 = xdup[b][tt][1];
                unsigned long long x2 = xdup[b][tt][2];
                aif[b] = ffma2(x0, wxif[0], ffma2(x1, wxif[1], ffma2(x2, wxif[2], bias_if)));
                ago[b] = ffma2(x0, wxgo[0], ffma2(x1, wxgo[1], ffma2(x2, wxgo[2], bias_go)));
            }

            // ---- recurrent matvec: 4 gates x 32 k, f32x2 packed over gate pairs ----
#pragma unroll
            for (int k = 0; k < HDIM; k += 2) {
#pragma unroll
                for (int b = 0; b < NB; b++) {
                    ulonglong2 hd = *reinterpret_cast<const ulonglong2*>(&hdup[b][k]);
                    aif[b] = ffma2(wif[k],     hd.x, aif[b]);
                    ago[b] = ffma2(wgo[k],     hd.x, ago[b]);
                    aif[b] = ffma2(wif[k + 1], hd.y, aif[b]);
                    ago[b] = ffma2(wgo[k + 1], hd.y, ago[b]);
                }
            }
            __syncwarp();   // all lanes done reading hdup before overwrite

            // ---- activations + state update ----
#pragma unroll
            for (int b = 0; b < NB; b++) {
                float ip, fp, gp, op;
                unpack2(aif[b], ip, fp);
                unpack2(ago[b], gp, op);
                float ig = fast_sig(ip);
                float fg = fast_sig(fp);
                float gg = fast_tanh(gp);
                float og = fast_sig(op);
                c[b] = fmaf(fg, c[b], ig * gg);
                h[b] = og * fast_tanh(c[b]);
                hdup[b][lane] = pack2(h[b], h[b]);
            }
            __syncwarp();   // writes visible before next step's reads
        }
    }

#pragma unroll
    for (int b = 0; b < NB; b++)
        out[(size_t)(b0 + b) * HDIM + lane] = h[b];
}

extern "C" void kernel_launch(void* const* d_in, const int* in_sizes, int n_in,
                              void* d_out, int out_size)
{
    const float* x    = (const float*)d_in[0];
    const float* W_ih = (const float*)d_in[1];
    const float* W_hh = (const float*)d_in[2];
    const float* b_ih = (const float*)d_in[3];
    const float* b_hh = (const float*)d_in[4];
    float* out = (float*)d_out;

    lstm_warp_kernel<<<BATCH / NB, 32>>>(x, W_ih, W_hh, b_ih, b_hh, out);
}

// round 2
// speedup vs baseline: 1.1676x; 1.1676x over previous
#include <cuda_runtime.h>
#include <cuda_bf16.h>

#define TSEQ   2048
#define BATCH  4096
#define HDIM   32
#define NB     4      // batch rows per warp
#define STAGE  16     // timesteps staged per x-load
#define NSTAGE (TSEQ / STAGE)

// ---------- packed f32x2 helpers ----------
__device__ __forceinline__ unsigned long long pack2(float lo, float hi) {
    unsigned long long r;
    asm("mov.b64 %0, {%1, %2};" : "=l"(r) : "f"(lo), "f"(hi));
    return r;
}
__device__ __forceinline__ void unpack2(unsigned long long v, float& lo, float& hi) {
    asm("mov.b64 {%0, %1}, %2;" : "=f"(lo), "=f"(hi) : "l"(v));
}
__device__ __forceinline__ unsigned long long ffma2(unsigned long long a,
                                                    unsigned long long b,
                                                    unsigned long long c) {
    unsigned long long d;
    asm("fma.rn.f32x2 %0, %1, %2, %3;" : "=l"(d) : "l"(a), "l"(b), "l"(c));
    return d;
}

// ---------- single-MUFU tanh (sm_75+) ----------
__device__ __forceinline__ float tanhf_fast(float x) {
    float y;
    asm("tanh.approx.f32 %0, %1;" : "=f"(y) : "f"(x));
    return y;
}
// sigmoid(x) = 0.5*tanh(x/2) + 0.5 ; the /2 is pre-folded into weights+bias,
// so callers pass the already-halved preactivation.
__device__ __forceinline__ float sig_from_half(float xh) {
    return fmaf(0.5f, tanhf_fast(xh), 0.5f);
}

// One warp per block; warp handles NB consecutive batch rows.
// Lane j owns h-index j. Gates packed (i,f) and (g,o) into f32x2.
// i,f,o gate weights/biases pre-scaled by 0.5 (sigmoid-via-tanh trick).
__global__ void __launch_bounds__(32, 1)
lstm_warp_kernel(const float* __restrict__ x,
                 const float* __restrict__ W_ih,
                 const float* __restrict__ W_hh,
                 const float* __restrict__ b_ih,
                 const float* __restrict__ b_hh,
                 float* __restrict__ out)
{
    // h duplicated (v,v); double-buffered so one __syncwarp per step suffices
    __shared__ __align__(16) unsigned long long hdup[2][NB][HDIM];
    // x staged duplicated; double-buffered for cross-stage prefetch
    __shared__ __align__(16) unsigned long long xdup[2][NB][STAGE][4];

    const int lane = threadIdx.x & 31;
    const int b0   = blockIdx.x * NB;

    // PyTorch gate rows for this lane: i, f, g, o
    const int r0 = lane;            // i  (sigmoid -> scale 0.5)
    const int r1 = HDIM + lane;     // f  (sigmoid -> scale 0.5)
    const int r2 = 2 * HDIM + lane; // g  (tanh    -> scale 1.0)
    const int r3 = 3 * HDIM + lane; // o  (sigmoid -> scale 0.5)

    // ---- preload weights into registers, gate-pair packed, sigmoid rows halved ----
    unsigned long long wif[HDIM], wgo[HDIM];
#pragma unroll
    for (int k = 0; k < HDIM; k++) {
        wif[k] = pack2(0.5f * W_hh[r0 * HDIM + k], 0.5f * W_hh[r1 * HDIM + k]);
        wgo[k] = pack2(       W_hh[r2 * HDIM + k], 0.5f * W_hh[r3 * HDIM + k]);
    }
    unsigned long long wxif[3], wxgo[3];
#pragma unroll
    for (int i = 0; i < 3; i++) {
        wxif[i] = pack2(0.5f * W_ih[r0 * 3 + i], 0.5f * W_ih[r1 * 3 + i]);
        wxgo[i] = pack2(       W_ih[r2 * 3 + i], 0.5f * W_ih[r3 * 3 + i]);
    }
    const unsigned long long bias_if = pack2(0.5f * (b_ih[r0] + b_hh[r0]),
                                             0.5f * (b_ih[r1] + b_hh[r1]));
    const unsigned long long bias_go = pack2(       (b_ih[r2] + b_hh[r2]),
                                             0.5f * (b_ih[r3] + b_hh[r3]));

    float c[NB], h[NB];
#pragma unroll
    for (int b = 0; b < NB; b++) {
        c[b] = 0.0f;
        h[b] = 0.0f;
        hdup[0][b][lane] = 0ull;
    }

    // ---- preload stage 0 of x (192 floats = 6 per lane, exact) ----
    {
#pragma unroll
        for (int it = 0; it < 6; it++) {
            int idx = it * 32 + lane;         // 0..191
            int b   = idx / (STAGE * 3);
            int rem = idx % (STAGE * 3);
            float v = x[(size_t)(b0 + b) * TSEQ * 3 + rem];
            xdup[0][b][rem / 3][rem % 3] = pack2(v, v);
        }
    }
    __syncwarp();

    int buf = 0;
    for (int s = 0; s < NSTAGE; s++) {
        // ---- prefetch next stage's x into registers (latency hides behind 16 steps) ----
        float xr[6];
        if (s + 1 < NSTAGE) {
#pragma unroll
            for (int it = 0; it < 6; it++) {
                int idx = it * 32 + lane;
                int b   = idx / (STAGE * 3);
                int rem = idx % (STAGE * 3);
                xr[it] = x[(size_t)(b0 + b) * TSEQ * 3 + (size_t)(s + 1) * STAGE * 3 + rem];
            }
        }

#pragma unroll 1
        for (int tt = 0; tt < STAGE; tt++) {
            const int rb = tt & 1;        // read h buffer
            const int wb = rb ^ 1;        // write h buffer

            unsigned long long aif[NB], ago[NB];

            // ---- input contribution + bias ----
#pragma unroll
            for (int b = 0; b < NB; b++) {
                ulonglong2 x01 = *reinterpret_cast<const ulonglong2*>(&xdup[buf][b][tt][0]);
                unsigned long long x2 = xdup[buf][b][tt][2];
                aif[b] = ffma2(x01.x, wxif[0], ffma2(x01.y, wxif[1], ffma2(x2, wxif[2], bias_if)));
                ago[b] = ffma2(x01.x, wxgo[0], ffma2(x01.y, wxgo[1], ffma2(x2, wxgo[2], bias_go)));
            }

            // ---- recurrent matvec: 4 gates x 32 k, f32x2 packed over gate pairs ----
#pragma unroll
            for (int k = 0; k < HDIM; k += 2) {
#pragma unroll
                for (int b = 0; b < NB; b++) {
                    ulonglong2 hd = *reinterpret_cast<const ulonglong2*>(&hdup[rb][b][k]);
                    aif[b] = ffma2(wif[k],     hd.x, aif[b]);
                    ago[b] = ffma2(wgo[k],     hd.x, ago[b]);
                    aif[b] = ffma2(wif[k + 1], hd.y, aif[b]);
                    ago[b] = ffma2(wgo[k + 1], hd.y, ago[b]);
                }
            }

            // ---- activations + state update (preacts for i,f,o already halved) ----
#pragma unroll
            for (int b = 0; b < NB; b++) {
                float ih, fh, gp, oh;
                unpack2(aif[b], ih, fh);
                unpack2(ago[b], gp, oh);
                float ig = sig_from_half(ih);
                float fg = sig_from_half(fh);
                float gg = tanhf_fast(gp);
                float og = sig_from_half(oh);
                c[b] = fmaf(fg, c[b], ig * gg);
                h[b] = og * tanhf_fast(c[b]);
                hdup[wb][b][lane] = pack2(h[b], h[b]);
            }
            __syncwarp();   // h writes visible before next step's reads
        }

        // ---- commit prefetched x into the other buffer ----
        if (s + 1 < NSTAGE) {
#pragma unroll
            for (int it = 0; it < 6; it++) {
                int idx = it * 32 + lane;
                int b   = idx / (STAGE * 3);
                int rem = idx % (STAGE * 3);
                xdup[buf ^ 1][b][rem / 3][rem % 3] = pack2(xr[it], xr[it]);
            }
            __syncwarp();
            buf ^= 1;
        }
    }

#pragma unroll
    for (int b = 0; b < NB; b++)
        out[(size_t)(b0 + b) * HDIM + lane] = h[b];
}

extern "C" void kernel_launch(void* const* d_in, const int* in_sizes, int n_in,
                              void* d_out, int out_size)
{
    const float* x    = (const float*)d_in[0];
    const float* W_ih = (const float*)d_in[1];
    const float* W_hh = (const float*)d_in[2];
    const float* b_ih = (const float*)d_in[3];
    const float* b_hh = (const float*)d_in[4];
    float* out = (float*)d_out;

    lstm_warp_kernel<<<BATCH / NB, 32>>>(x, W_ih, W_hh, b_ih, b_hh, out);
}